// round 16
// baseline (speedup 1.0000x reference)
#include <cuda_runtime.h>
#include <cuda_fp16.h>
#include <math.h>
#include <stdint.h>

// Problem constants
#define NB 4
#define LQ 2048
#define SK 4096
#define CC 256
#define HH 8
#define DD 32
#define HID 1024

// ---------------- scratch (device globals; no allocation allowed) ----------------
__device__ float  g_tgt [NB * LQ * CC];   // running residual (fp32)
__device__ __half g_tmp_h[NB * LQ * CC];  // LN output (half)
__device__ __half g_qk_h [NB * LQ * CC];  // tgt2 + tgt_pos (half)
__device__ float  g_q  [NB * LQ * CC];    // linear-attn feature Q (fp32)
__device__ float  g_k  [NB * LQ * CC];
__device__ float  g_v  [NB * LQ * CC];
__device__ __half g_ao_h[NB * LQ * CC];   // attention outputs (half)
__device__ __half g_qc_h[NB * LQ * CC];   // cross-attn Q (half)
__device__ __half g_ck_h[NB * SK * CC];
__device__ __half g_cv_h[NB * SK * CC];
__device__ float  g_kv [NB * HH * DD * DD];
__device__ float  g_ks [NB * HH * DD];
__device__ __half g_h_h [NB * LQ * HID];
__device__ __half g_h2_h[NB * LQ * HID];

// ---------------- fp16 m16n8k16 mma (f32 accum) ----------------
__device__ __forceinline__ void mma_f16(float c[4], const uint32_t a[4],
                                        uint32_t b0, uint32_t b1) {
    asm volatile(
        "mma.sync.aligned.m16n8k16.row.col.f32.f16.f16.f32 "
        "{%0,%1,%2,%3}, {%4,%5,%6,%7}, {%8,%9}, {%0,%1,%2,%3};\n"
        : "+f"(c[0]), "+f"(c[1]), "+f"(c[2]), "+f"(c[3])
        : "r"(a[0]), "r"(a[1]), "r"(a[2]), "r"(a[3]),
          "r"(b0), "r"(b1));
}

__device__ __forceinline__ uint32_t pack_h2(float lo, float hi) {
    __half2 h = __floats2half2_rn(lo, hi);
    return *(uint32_t*)&h;
}

__device__ __forceinline__ uint32_t ex2_h2(uint32_t x) {
    uint32_t r;
    asm("ex2.approx.f16x2 %0, %1;" : "=r"(r) : "r"(x));
    return r;
}

__device__ __forceinline__ void ldsm_x4(uint32_t r[4], uint32_t addr) {
    asm volatile("ldmatrix.sync.aligned.m8n8.x4.shared.b16 {%0,%1,%2,%3}, [%4];"
        : "=r"(r[0]), "=r"(r[1]), "=r"(r[2]), "=r"(r[3]) : "r"(addr));
}

__device__ __forceinline__ void ldsm_x4_t(uint32_t r[4], uint32_t addr) {
    asm volatile("ldmatrix.sync.aligned.m8n8.x4.trans.shared.b16 {%0,%1,%2,%3}, [%4];"
        : "=r"(r[0]), "=r"(r[1]), "=r"(r[2]), "=r"(r[3]) : "r"(addr));
}

// ---------------- LayerNorm: warp per row, half outputs ----------------
__global__ __launch_bounds__(256) void ln_kernel(
    const float* __restrict__ x, const float* __restrict__ g,
    const float* __restrict__ b, const float* __restrict__ pos,
    __half* __restrict__ lnout, __half* __restrict__ qkout,
    float* __restrict__ copyout)
{
    int w = threadIdx.x >> 5, lane = threadIdx.x & 31;
    int row = blockIdx.x * 8 + w;
    size_t base = (size_t)row * CC;
    int c0 = lane * 4, c1 = 128 + lane * 4;

    float4 v0 = *(const float4*)(x + base + c0);
    float4 v1 = *(const float4*)(x + base + c1);
    if (copyout) {
        *(float4*)(copyout + base + c0) = v0;
        *(float4*)(copyout + base + c1) = v1;
    }
    float s = v0.x + v0.y + v0.z + v0.w + v1.x + v1.y + v1.z + v1.w;
    #pragma unroll
    for (int o = 16; o; o >>= 1) s += __shfl_xor_sync(0xffffffffu, s, o);
    float mean = s * (1.0f / CC);
    float d0x = v0.x - mean, d0y = v0.y - mean, d0z = v0.z - mean, d0w = v0.w - mean;
    float d1x = v1.x - mean, d1y = v1.y - mean, d1z = v1.z - mean, d1w = v1.w - mean;
    float vs = d0x*d0x + d0y*d0y + d0z*d0z + d0w*d0w
             + d1x*d1x + d1y*d1y + d1z*d1z + d1w*d1w;
    #pragma unroll
    for (int o = 16; o; o >>= 1) vs += __shfl_xor_sync(0xffffffffu, vs, o);
    float rstd = rsqrtf(vs * (1.0f / CC) + 1e-5f);

    float4 g0 = *(const float4*)(g + c0), g1 = *(const float4*)(g + c1);
    float4 b0 = *(const float4*)(b + c0), b1 = *(const float4*)(b + c1);
    float4 y0, y1;
    y0.x = d0x * rstd * g0.x + b0.x;  y0.y = d0y * rstd * g0.y + b0.y;
    y0.z = d0z * rstd * g0.z + b0.z;  y0.w = d0w * rstd * g0.w + b0.w;
    y1.x = d1x * rstd * g1.x + b1.x;  y1.y = d1y * rstd * g1.y + b1.y;
    y1.z = d1z * rstd * g1.z + b1.z;  y1.w = d1w * rstd * g1.w + b1.w;
    uint2 o0, o1;
    o0.x = pack_h2(y0.x, y0.y); o0.y = pack_h2(y0.z, y0.w);
    o1.x = pack_h2(y1.x, y1.y); o1.y = pack_h2(y1.z, y1.w);
    *(uint2*)(lnout + base + c0) = o0;
    *(uint2*)(lnout + base + c1) = o1;
    if (qkout) {
        float4 p0 = *(const float4*)(pos + base + c0);
        float4 p1 = *(const float4*)(pos + base + c1);
        uint2 q0v, q1v;
        q0v.x = pack_h2(y0.x + p0.x, y0.y + p0.y);
        q0v.y = pack_h2(y0.z + p0.z, y0.w + p0.w);
        q1v.x = pack_h2(y1.x + p1.x, y1.y + p1.y);
        q1v.y = pack_h2(y1.z + p1.z, y1.w + p1.w);
        *(uint2*)(qkout + base + c0) = q0v;
        *(uint2*)(qkout + base + c1) = q1v;
    }
}

// ---------------- GEMM common bits ----------------
// flags: 2 = C half, 4 = elu+1 epilogue
struct GemmP {
    const void* A; const float* B; const float* bias; const float* res;
    void* C; int flags;
};

#define GEMM_EPILOGUE()                                                         \
    _Pragma("unroll")                                                           \
    for (int s = 0; s < 2; s++) {                                               \
        int r = bm + m0 + 16 * s + g;                                           \
        _Pragma("unroll")                                                       \
        for (int jn = 0; jn < 4; jn++) {                                        \
            int cc0 = bn + n0 + 8 * jn + 2 * tig;                               \
            float v0 = acc[s][jn][0], v1 = acc[s][jn][1];                       \
            float v2 = acc[s][jn][2], v3 = acc[s][jn][3];                       \
            if (P.bias) {                                                       \
                float bb0 = P.bias[cc0], bb1 = P.bias[cc0 + 1];                 \
                v0 += bb0; v1 += bb1; v2 += bb0; v3 += bb1;                     \
            }                                                                   \
            size_t o0 = (size_t)r * Nn + cc0;                                   \
            size_t o1 = (size_t)(r + 8) * Nn + cc0;                             \
            if (P.res) {                                                        \
                v0 += P.res[o0]; v1 += P.res[o0 + 1];                           \
                v2 += P.res[o1]; v3 += P.res[o1 + 1];                           \
            }                                                                   \
            if (P.flags & 4) {                                                  \
                v0 = v0 > 0.f ? v0 + 1.0f : expf(v0);                           \
                v1 = v1 > 0.f ? v1 + 1.0f : expf(v1);                           \
                v2 = v2 > 0.f ? v2 + 1.0f : expf(v2);                           \
                v3 = v3 > 0.f ? v3 + 1.0f : expf(v3);                           \
            }                                                                   \
            if (P.flags & 2) {                                                  \
                __half* Ch = (__half*)P.C;                                      \
                *(uint32_t*)(Ch + o0) = pack_h2(v0, v1);                        \
                *(uint32_t*)(Ch + o1) = pack_h2(v2, v3);                        \
            } else {                                                            \
                float* Cf = (float*)P.C;                                        \
                *(float2*)(Cf + o0) = make_float2(v0, v1);                      \
                *(float2*)(Cf + o1) = make_float2(v2, v3);                      \
            }                                                                   \
        }                                                                       \
    }

// ---------------- fp16-A GEMM, 128x64 tile, 256 threads, ldmatrix ----------------
__global__ __launch_bounds__(256) void gemm_h2(
    GemmP p0, GemmP p1, GemmP p2, int M, int Nn, int K)
{
    const GemmP P = (blockIdx.z == 0) ? p0 : ((blockIdx.z == 1) ? p1 : p2);
    __shared__ __align__(16) __half Ah[2][128][24];  // [m][k], 48B row stride
    __shared__ __align__(16) __half Bh[2][16][72];   // [k][n], 144B row stride
    const int A_BUF = 128 * 24 * 2;
    const int B_BUF = 16 * 72 * 2;
    const int tid = threadIdx.x;
    const int w = tid >> 5, lane = tid & 31;
    const int wy = w >> 1, wx = w & 1;
    const int bm = blockIdx.y * 128, bn = blockIdx.x * 64;
    const int m0 = wy * 32, n0 = wx * 32;
    const int g = lane >> 2, tig = lane & 3;
    const __half* Ag = (const __half*)P.A;

    float acc[2][4][4];
    #pragma unroll
    for (int s = 0; s < 2; s++)
        #pragma unroll
        for (int j = 0; j < 4; j++)
            #pragma unroll
            for (int q = 0; q < 4; q++) acc[s][j][q] = 0.f;

    uint32_t aAddr[2], bAddr;
    #pragma unroll
    for (int s = 0; s < 2; s++)
        aAddr[s] = (uint32_t)__cvta_generic_to_shared(
            &Ah[0][m0 + 16 * s + (lane & 15)][(lane >> 4) * 8]);
    bAddr = (uint32_t)__cvta_generic_to_shared(
        &Bh[0][lane & 15][n0 + (lane >> 4) * 8]);

    // A: 128 rows x 16 k halves = 2048; 256 threads x uint4(8 halves).
    const int arow = tid >> 1, akq = (tid & 1) * 8;
    // B: 16 rows x 64 n floats = 1024; 256 threads x float4.
    const int brow = tid >> 4, bnq = (tid & 15) * 4;
    uint4 ra;
    float4 rb;
    ra = *(const uint4*)(Ag + (size_t)(bm + arow) * K + akq);
    rb = *(const float4*)(P.B + (size_t)brow * Nn + bn + bnq);

    int p = 0;
    for (int k0 = 0; k0 < K; k0 += 16) {
        *(uint4*)&Ah[p][arow][akq] = ra;
        {
            uint2 bv;
            bv.x = pack_h2(rb.x, rb.y);
            bv.y = pack_h2(rb.z, rb.w);
            *(uint2*)&Bh[p][brow][bnq] = bv;
        }
        __syncthreads();
        if (k0 + 16 < K) {
            ra = *(const uint4*)(Ag + (size_t)(bm + arow) * K + k0 + 16 + akq);
            rb = *(const float4*)(P.B + (size_t)(k0 + 16 + brow) * Nn + bn + bnq);
        }
        uint32_t af[2][4], bf0[4], bf1[4];
        ldsm_x4(af[0], aAddr[0] + p * A_BUF);
        ldsm_x4(af[1], aAddr[1] + p * A_BUF);
        ldsm_x4_t(bf0, bAddr + p * B_BUF);
        ldsm_x4_t(bf1, bAddr + 32 + p * B_BUF);
        #pragma unroll
        for (int s = 0; s < 2; s++) {
            mma_f16(acc[s][0], af[s], bf0[0], bf0[1]);
            mma_f16(acc[s][1], af[s], bf0[2], bf0[3]);
            mma_f16(acc[s][2], af[s], bf1[0], bf1[1]);
            mma_f16(acc[s][3], af[s], bf1[2], bf1[3]);
        }
        p ^= 1;
    }
    GEMM_EPILOGUE()
}

// ---------------- fp32-A (+pos_embed) GEMM, 128x64 tile ----------------
__global__ __launch_bounds__(256) void gemm_f2(
    GemmP p0, GemmP p1, GemmP p2, int M, int Nn, int K,
    const float* __restrict__ pe)
{
    const GemmP P = (blockIdx.z == 0) ? p0 : ((blockIdx.z == 1) ? p1 : p2);
    __shared__ __align__(16) __half Ah[2][128][24];
    __shared__ __align__(16) __half Bh[2][16][72];
    const int A_BUF = 128 * 24 * 2;
    const int B_BUF = 16 * 72 * 2;
    const int tid = threadIdx.x;
    const int w = tid >> 5, lane = tid & 31;
    const int wy = w >> 1, wx = w & 1;
    const int bm = blockIdx.y * 128, bn = blockIdx.x * 64;
    const int m0 = wy * 32, n0 = wx * 32;
    const int g = lane >> 2, tig = lane & 3;
    const float* Ag = (const float*)P.A;

    float acc[2][4][4];
    #pragma unroll
    for (int s = 0; s < 2; s++)
        #pragma unroll
        for (int j = 0; j < 4; j++)
            #pragma unroll
            for (int q = 0; q < 4; q++) acc[s][j][q] = 0.f;

    uint32_t aAddr[2], bAddr;
    #pragma unroll
    for (int s = 0; s < 2; s++)
        aAddr[s] = (uint32_t)__cvta_generic_to_shared(
            &Ah[0][m0 + 16 * s + (lane & 15)][(lane >> 4) * 8]);
    bAddr = (uint32_t)__cvta_generic_to_shared(
        &Bh[0][lane & 15][n0 + (lane >> 4) * 8]);

    // A: 128 rows x 16 k floats = 2048; 2 iterations of 256 threads x float4.
    // B: 16 x 64 floats; 256 threads x float4.
    const int brow = tid >> 4, bnq = (tid & 15) * 4;
    float4 ra[2], rb;
    #pragma unroll
    for (int i = 0; i < 2; i++) {
        int c = tid + i * 256;
        int arow = c >> 2, akq = (c & 3) * 4;
        ra[i] = *(const float4*)(Ag + (size_t)(bm + arow) * K + akq);
        if (pe) {
            float4 pv = *(const float4*)(pe + ((size_t)((bm + arow) & (SK - 1))) * CC + akq);
            ra[i].x += pv.x; ra[i].y += pv.y; ra[i].z += pv.z; ra[i].w += pv.w;
        }
    }
    rb = *(const float4*)(P.B + (size_t)brow * Nn + bn + bnq);

    int p = 0;
    for (int k0 = 0; k0 < K; k0 += 16) {
        #pragma unroll
        for (int i = 0; i < 2; i++) {
            int c = tid + i * 256;
            int arow = c >> 2, akq = (c & 3) * 4;
            uint2 av;
            av.x = pack_h2(ra[i].x, ra[i].y);
            av.y = pack_h2(ra[i].z, ra[i].w);
            *(uint2*)&Ah[p][arow][akq] = av;
        }
        {
            uint2 bv;
            bv.x = pack_h2(rb.x, rb.y);
            bv.y = pack_h2(rb.z, rb.w);
            *(uint2*)&Bh[p][brow][bnq] = bv;
        }
        __syncthreads();
        if (k0 + 16 < K) {
            #pragma unroll
            for (int i = 0; i < 2; i++) {
                int c = tid + i * 256;
                int arow = c >> 2, akq = (c & 3) * 4;
                ra[i] = *(const float4*)(Ag + (size_t)(bm + arow) * K + k0 + 16 + akq);
                if (pe) {
                    float4 pv = *(const float4*)(pe + ((size_t)((bm + arow) & (SK - 1))) * CC + k0 + 16 + akq);
                    ra[i].x += pv.x; ra[i].y += pv.y; ra[i].z += pv.z; ra[i].w += pv.w;
                }
            }
            rb = *(const float4*)(P.B + (size_t)(k0 + 16 + brow) * Nn + bn + bnq);
        }
        uint32_t af[2][4], bf0[4], bf1[4];
        ldsm_x4(af[0], aAddr[0] + p * A_BUF);
        ldsm_x4(af[1], aAddr[1] + p * A_BUF);
        ldsm_x4_t(bf0, bAddr + p * B_BUF);
        ldsm_x4_t(bf1, bAddr + 32 + p * B_BUF);
        #pragma unroll
        for (int s = 0; s < 2; s++) {
            mma_f16(acc[s][0], af[s], bf0[0], bf0[1]);
            mma_f16(acc[s][1], af[s], bf0[2], bf0[3]);
            mma_f16(acc[s][2], af[s], bf1[0], bf1[1]);
            mma_f16(acc[s][3], af[s], bf1[2], bf1[3]);
        }
        p ^= 1;
    }
    GEMM_EPILOGUE()
}

// ---------------- linear attention: partial KV, register-prefetched stages ------
__global__ __launch_bounds__(256) void kv_part_kernel(
    const float* __restrict__ Kf, const float* __restrict__ V,
    float* __restrict__ KV, float* __restrict__ Ksum)
{
    int h = blockIdx.x, n = blockIdx.y, ch = blockIdx.z;   // ch 0..31
    int t = threadIdx.x;
    int d = t >> 3;
    int e4 = (t & 7) * 4;
    __shared__ float ks[16][32], vs[16][32];
    float4 acc = make_float4(0.f, 0.f, 0.f, 0.f);
    float ka = 0.f;
    const int rows = LQ / 32;
    int sbase = ch * rows;
    int r = t >> 5, c = t & 31;
    size_t gbase = (size_t)(n * LQ + sbase) * CC + h * DD + c;

    float pk0 = Kf[gbase + (size_t)r * CC];
    float pk1 = Kf[gbase + (size_t)(r + 8) * CC];
    float pv0 = V[gbase + (size_t)r * CC];
    float pv1 = V[gbase + (size_t)(r + 8) * CC];

    for (int s0 = 0; s0 < rows; s0 += 16) {
        __syncthreads();
        ks[r][c] = pk0; ks[r + 8][c] = pk1;
        vs[r][c] = pv0; vs[r + 8][c] = pv1;
        __syncthreads();
        if (s0 + 16 < rows) {
            size_t gb = gbase + (size_t)(s0 + 16) * CC;
            pk0 = Kf[gb + (size_t)r * CC];
            pk1 = Kf[gb + (size_t)(r + 8) * CC];
            pv0 = V[gb + (size_t)r * CC];
            pv1 = V[gb + (size_t)(r + 8) * CC];
        }
        #pragma unroll
        for (int j = 0; j < 16; j++) {
            float kv = ks[j][d];
            float4 v4 = *(const float4*)&vs[j][e4];
            acc.x += kv * v4.x; acc.y += kv * v4.y;
            acc.z += kv * v4.z; acc.w += kv * v4.w;
            ka += kv;
        }
    }
    float* kvp = &KV[((size_t)(n * HH + h) * DD + d) * DD + e4];
    atomicAdd(kvp + 0, acc.x);
    atomicAdd(kvp + 1, acc.y);
    atomicAdd(kvp + 2, acc.z);
    atomicAdd(kvp + 3, acc.w);
    if (e4 == 0) atomicAdd(&Ksum[(n * HH + h) * DD + d], ka);
}

// ---------------- linear attention output: per-head CTAs, 32 tokens --------------
// grid (NB*LQ/32, HH), 256 threads. Warp w owns tokens [4w, 4w+4); lane = e.
__global__ __launch_bounds__(256) void lin_out_kernel(
    const float* __restrict__ Qf, const float* __restrict__ KV,
    const float* __restrict__ Ksum, __half* __restrict__ AO)
{
    __shared__ float kvs[DD][DD];   // 4KB, this head only
    __shared__ float kss[DD];
    __shared__ float qs[32][33];    // [token][d], padded
    int bx = blockIdx.x, h = blockIdx.y;
    int n = bx >> 6;                // 64 CTAs per batch (2048/32)
    int l0 = (bx & 63) * 32;
    int t = threadIdx.x;
    int lane = t & 31, w = t >> 5;

    // load this head's KV block (1024 floats) + Ksum (32)
    for (int i = t; i < DD * DD; i += 256)
        kvs[i >> 5][i & 31] = KV[((size_t)(n * HH + h) * DD * DD) + i];
    if (t < DD) kss[t] = Ksum[(n * HH + h) * DD + t];
    // load 32 tokens x 32 dims of Q (head slice)
    #pragma unroll
    for (int i = 0; i < 4; i++) {
        int tok = w + i * 8;
        qs[tok][lane] = Qf[(size_t)(n * LQ + l0 + tok) * CC + h * DD + lane];
    }
    __syncthreads();

    // warp w handles tokens 4w..4w+3; lane = output dim e
    int e = lane;
    float z0 = 0.f, z1 = 0.f, z2 = 0.f, z3 = 0.f;
    float a0 = 0.f, a1 = 0.f, a2 = 0.f, a3 = 0.f;
    int tok0 = w * 4;
    #pragma unroll
    for (int d = 0; d < 32; d++) {
        float kv = kvs[d][e];
        float kd = kss[d];
        float q0 = qs[tok0 + 0][d];
        float q1 = qs[tok0 + 1][d];
        float q2 = qs[tok0 + 2][d];
        float q3 = qs[tok0 + 3][d];
        z0 += q0 * kd; a0 += q0 * kv;
        z1 += q1 * kd; a1 += q1 * kv;
        z2 += q2 * kd; a2 += q2 * kv;
        z3 += q3 * kd; a3 += q3 * kv;
    }
    size_t ob = (size_t)(n * LQ + l0 + tok0) * CC + h * DD + e;
    AO[ob]          = __float2half_rn(a0 / (z0 + 1e-6f));
    AO[ob + CC]     = __float2half_rn(a1 / (z1 + 1e-6f));
    AO[ob + 2 * CC] = __float2half_rn(a2 / (z2 + 1e-6f));
    AO[ob + 3 * CC] = __float2half_rn(a3 / (z3 + 1e-6f));
}

// ---------------- fp16 flash cross-attention, base-2 softmax, mma denominator ---
__global__ __launch_bounds__(256) void cross_attn_tc(
    const __half* __restrict__ Qh, const __half* __restrict__ Kh,
    const __half* __restrict__ Vh, __half* __restrict__ Oh)
{
    __shared__ __half Ks[2][64][40];   // [key][dim]
    __shared__ __half Vt[2][40][72];   // [dim][key]; dims 32..39: ones row + zeros
    const int n = blockIdx.z, h = blockIdx.y, q0 = blockIdx.x * 128;
    const int tid = threadIdx.x;
    const int w = tid >> 5, lane = tid & 31;
    const int g = lane >> 2, tig = lane & 3;
    const float scale = 0.17677669529663687f * 1.4426950408889634f;

    for (int i = tid; i < 2 * 8 * 72; i += 256) {
        int bsel = i / (8 * 72);
        int rr = (i / 72) % 8;
        int cc = i % 72;
        Vt[bsel][32 + rr][cc] = (rr == 0) ? __float2half(1.0f) : __float2half(0.0f);
    }

    uint32_t qf[2][4];
    {
        int r0 = q0 + w * 16 + g;
        const __half* qp = Qh + ((size_t)n * LQ + r0) * CC + h * DD;
        #pragma unroll
        for (int kt = 0; kt < 2; kt++) {
            int d0 = kt * 16;
            #pragma unroll
            for (int q = 0; q < 4; q++) {
                int off = ((q & 1) ? 8 * CC : 0) + d0 + ((q >> 1) ? 8 : 0) + 2 * tig;
                __half2 hv = *(const __half2*)(qp + off);
                float2 fv = __half22float2(hv);
                qf[kt][q] = pack_h2(fv.x * scale, fv.y * scale);
            }
        }
    }

    float accO[4][4];
    #pragma unroll
    for (int j = 0; j < 4; j++)
        #pragma unroll
        for (int q = 0; q < 4; q++) accO[j][q] = 0.f;
    float accX[4] = {0.f, 0.f, 0.f, 0.f};

    const size_t kvbase = (size_t)n * SK * CC + h * DD;

    uint2 kp[2], vp[2];
    #pragma unroll
    for (int i = 0; i < 2; i++) {
        int lin = tid + i * 256;
        int row = lin >> 3, cq = (lin & 7) * 4;
        kp[i] = *(const uint2*)(Kh + kvbase + (size_t)row * CC + cq);
        vp[i] = *(const uint2*)(Vh + kvbase + (size_t)row * CC + cq);
    }

    int p = 0;
    for (int s0 = 0; s0 < SK; s0 += 64) {
        #pragma unroll
        for (int i = 0; i < 2; i++) {
            int lin = tid + i * 256;
            int row = lin >> 3, cq = (lin & 7) * 4;
            *(uint2*)&Ks[p][row][cq] = kp[i];
            __half2 v01 = *(__half2*)&vp[i].x;
            __half2 v23 = *(__half2*)&vp[i].y;
            Vt[p][cq + 0][row] = __low2half(v01);
            Vt[p][cq + 1][row] = __high2half(v01);
            Vt[p][cq + 2][row] = __low2half(v23);
            Vt[p][cq + 3][row] = __high2half(v23);
        }
        __syncthreads();
        if (s0 + 64 < SK) {
            #pragma unroll
            for (int i = 0; i < 2; i++) {
                int lin = tid + i * 256;
                int row = lin >> 3, cq = (lin & 7) * 4;
                const size_t off = kvbase + (size_t)(s0 + 64 + row) * CC + cq;
                kp[i] = *(const uint2*)(Kh + off);
                vp[i] = *(const uint2*)(Vh + off);
            }
        }

        float accS[8][4];
        #pragma unroll
        for (int j = 0; j < 8; j++)
            #pragma unroll
            for (int q = 0; q < 4; q++) accS[j][q] = 0.f;
        #pragma unroll
        for (int j = 0; j < 8; j++) {
            #pragma unroll
            for (int kt = 0; kt < 2; kt++) {
                int d0 = kt * 16;
                uint32_t b0 = *(const uint32_t*)&Ks[p][8 * j + g][d0 + 2 * tig];
                uint32_t b1 = *(const uint32_t*)&Ks[p][8 * j + g][d0 + 8 + 2 * tig];
                mma_f16(accS[j], qf[kt], b0, b1);
            }
        }

        uint32_t eh[8][2];
        #pragma unroll
        for (int j = 0; j < 8; j++) {
            eh[j][0] = ex2_h2(pack_h2(accS[j][0], accS[j][1]));
            eh[j][1] = ex2_h2(pack_h2(accS[j][2], accS[j][3]));
        }

        #pragma unroll
        for (int kt = 0; kt < 4; kt++) {
            uint32_t pa[4];
            pa[0] = eh[2 * kt][0];
            pa[1] = eh[2 * kt][1];
            pa[2] = eh[2 * kt + 1][0];
            pa[3] = eh[2 * kt + 1][1];
            int k0 = 16 * kt;
            #pragma unroll
            for (int jn = 0; jn < 4; jn++) {
                uint32_t b0 = *(const uint32_t*)&Vt[p][8 * jn + g][k0 + 2 * tig];
                uint32_t b1 = *(const uint32_t*)&Vt[p][8 * jn + g][k0 + 8 + 2 * tig];
                mma_f16(accO[jn], pa, b0, b1);
            }
            uint32_t b0x = *(const uint32_t*)&Vt[p][32 + g][k0 + 2 * tig];
            uint32_t b1x = *(const uint32_t*)&Vt[p][32 + g][k0 + 8 + 2 * tig];
            mma_f16(accX, pa, b0x, b1x);
        }
        p ^= 1;
    }

    int src = lane & 28;
    float l0 = __shfl_sync(0xffffffffu, accX[0], src);
    float l1 = __shfl_sync(0xffffffffu, accX[2], src);

    float inv0 = 1.0f / l0, inv1 = 1.0f / l1;
    int r0 = q0 + w * 16 + g;
    __half* op = Oh + ((size_t)n * LQ + r0) * CC + h * DD;
    #pragma unroll
    for (int jn = 0; jn < 4; jn++) {
        int c = 8 * jn + 2 * tig;
        *(uint32_t*)(op + c) = pack_h2(accO[jn][0] * inv0, accO[jn][1] * inv0);
        *(uint32_t*)(op + 8 * CC + c) = pack_h2(accO[jn][2] * inv1, accO[jn][3] * inv1);
    }
}

// ---------------- depthwise 3-tap conv + GELU, half in/out ----------------
__global__ __launch_bounds__(256) void dwconv_gelu_kernel(
    const __half* __restrict__ hin, const float* __restrict__ dwk,
    const float* __restrict__ dwb, __half* __restrict__ hout)
{
    int idx = blockIdx.x * 256 + threadIdx.x;  // over NB * (LQ/4) * HID
    int ch = idx & (HID - 1);
    int lg = idx >> 10;
    int l0 = (lg & (LQ / 4 - 1)) * 4;
    int nb = lg >> 9;
    size_t base = ((size_t)nb * LQ + l0) * HID + ch;

    float t0 = dwk[ch * 9 + 1];
    float t1 = dwk[ch * 9 + 4];
    float t2 = dwk[ch * 9 + 7];
    float bv = dwb[ch];

    float xm = (l0 > 0) ? __half2float(hin[base - HID]) : 0.f;
    float x0 = __half2float(hin[base]);
    float x1 = __half2float(hin[base + HID]);
    float x2 = __half2float(hin[base + 2 * HID]);
    float x3 = __half2float(hin[base + 3 * HID]);
    float x4 = (l0 + 4 < LQ) ? __half2float(hin[base + 4 * HID]) : 0.f;

    float y0 = xm * t0 + x0 * t1 + x1 * t2 + bv;
    float y1 = x0 * t0 + x1 * t1 + x2 * t2 + bv;
    float y2 = x1 * t0 + x2 * t1 + x3 * t2 + bv;
    float y3 = x2 * t0 + x3 * t1 + x4 * t2 + bv;

    const float is2 = 0.70710678118654752f;
    hout[base]           = __float2half_rn(0.5f * y0 * (1.0f + erff(y0 * is2)));
    hout[base + HID]     = __float2half_rn(0.5f * y1 * (1.0f + erff(y1 * is2)));
    hout[base + 2 * HID] = __float2half_rn(0.5f * y2 * (1.0f + erff(y2 * is2)));
    hout[base + 3 * HID] = __float2half_rn(0.5f * y3 * (1.0f + erff(y3 * is2)));
}

// ---------------- launch ----------------
extern "C" void kernel_launch(void* const* d_in, const int* in_sizes, int n_in,
                              void* d_out, int out_size)
{
    const float* tgt       = (const float*)d_in[0];
    const float* memory    = (const float*)d_in[1];
    const float* tgt_pos   = (const float*)d_in[2];
    const float* pos_embed = (const float*)d_in[3];
    const float* ln1_g = (const float*)d_in[4],  *ln1_b = (const float*)d_in[5];
    const float* ln2_g = (const float*)d_in[6],  *ln2_b = (const float*)d_in[7];
    const float* ln3_g = (const float*)d_in[8],  *ln3_b = (const float*)d_in[9];
    const float* wq = (const float*)d_in[10], *bq = (const float*)d_in[11];
    const float* wk = (const float*)d_in[12], *bk = (const float*)d_in[13];
    const float* wv = (const float*)d_in[14], *bv = (const float*)d_in[15];
    const float* w_merge = (const float*)d_in[16];
    const float* cwq = (const float*)d_in[17], *cbq = (const float*)d_in[18];
    const float* cwk = (const float*)d_in[19], *cbk = (const float*)d_in[20];
    const float* cwv = (const float*)d_in[21], *cbv = (const float*)d_in[22];
    const float* cwo = (const float*)d_in[23], *cbo = (const float*)d_in[24];
    const float* mw1 = (const float*)d_in[25], *mb1 = (const float*)d_in[26];
    const float* dwk = (const float*)d_in[27], *dwb = (const float*)d_in[28];
    const float* mw2 = (const float*)d_in[29], *mb2 = (const float*)d_in[30];

    float *p_tgt, *p_q, *p_k, *p_v, *p_kv, *p_ks;
    __half *p_tmp, *p_qk, *p_ao, *p_qc, *p_ck, *p_cv, *p_h, *p_h2;
    cudaGetSymbolAddress((void**)&p_tgt, g_tgt);
    cudaGetSymbolAddress((void**)&p_tmp, g_tmp_h);
    cudaGetSymbolAddress((void**)&p_qk,  g_qk_h);
    cudaGetSymbolAddress((void**)&p_q,   g_q);
    cudaGetSymbolAddress((void**)&p_k,   g_k);
    cudaGetSymbolAddress((void**)&p_v,   g_v);
    cudaGetSymbolAddress((void**)&p_ao,  g_ao_h);
    cudaGetSymbolAddress((void**)&p_qc,  g_qc_h);
    cudaGetSymbolAddress((void**)&p_ck,  g_ck_h);
    cudaGetSymbolAddress((void**)&p_cv,  g_cv_h);
    cudaGetSymbolAddress((void**)&p_kv,  g_kv);
    cudaGetSymbolAddress((void**)&p_ks,  g_ks);
    cudaGetSymbolAddress((void**)&p_h,   g_h_h);
    cudaGetSymbolAddress((void**)&p_h2,  g_h2_h);

    const int ML = NB * LQ;   // 8192
    const int MS = NB * SK;   // 16384

    // ---- self attention (linear attention) ----
    ln_kernel<<<ML / 8, 256>>>(tgt, ln1_g, ln1_b, tgt_pos, p_tmp, p_qk, p_tgt);
    {
        GemmP pq = {p_qk,  wq, bq, nullptr, p_q, 4};
        GemmP pk = {p_qk,  wk, bk, nullptr, p_k, 4};
        GemmP pv = {p_tmp, wv, bv, nullptr, p_v, 0};
        gemm_h2<<<dim3(CC / 64, ML / 128, 3), 256>>>(pq, pk, pv, ML, CC, CC);
    }
    cudaMemsetAsync(p_kv, 0, NB * HH * DD * DD * sizeof(float));
    cudaMemsetAsync(p_ks, 0, NB * HH * DD * sizeof(float));
    kv_part_kernel<<<dim3(HH, NB, 32), 256>>>(p_k, p_v, p_kv, p_ks);
    lin_out_kernel<<<dim3(NB * LQ / 32, HH), 256>>>(p_q, p_kv, p_ks, p_ao);
    {
        GemmP pm = {p_ao, w_merge, nullptr, p_tgt, p_tgt, 0};
        gemm_h2<<<dim3(CC / 64, ML / 128, 1), 256>>>(pm, pm, pm, ML, CC, CC);
    }

    // ---- cross attention (softmax MHA) ----
    ln_kernel<<<ML / 8, 256>>>(p_tgt, ln2_g, ln2_b, nullptr, p_tmp, nullptr, nullptr);
    {
        GemmP pq = {p_tmp, cwq, cbq, nullptr, p_qc, 2};
        gemm_h2<<<dim3(CC / 64, ML / 128, 1), 256>>>(pq, pq, pq, ML, CC, CC);
        GemmP pk = {memory, cwk, cbk, nullptr, p_ck, 2};
        GemmP pv = {memory, cwv, cbv, nullptr, p_cv, 2};
        gemm_f2<<<dim3(CC / 64, MS / 128, 2), 256>>>(pk, pv, pv, MS, CC, CC, pos_embed);
    }
    cross_attn_tc<<<dim3(LQ / 128, HH, NB), 256>>>(p_qc, p_ck, p_cv, p_ao);
    {
        GemmP po = {p_ao, cwo, cbo, p_tgt, p_tgt, 0};
        gemm_h2<<<dim3(CC / 64, ML / 128, 1), 256>>>(po, po, po, ML, CC, CC);
    }

    // ---- MLP ----
    ln_kernel<<<ML / 8, 256>>>(p_tgt, ln3_g, ln3_b, nullptr, p_tmp, nullptr, nullptr);
    {
        GemmP p1 = {p_tmp, mw1, mb1, nullptr, p_h, 2};
        gemm_h2<<<dim3(HID / 64, ML / 128, 1), 256>>>(p1, p1, p1, ML, HID, CC);
    }
    dwconv_gelu_kernel<<<NB * LQ * HID / 1024, 256>>>(p_h, dwk, dwb, p_h2);
    {
        GemmP p2 = {p_h2, mw2, mb2, p_tgt, (float*)d_out, 0};
        gemm_h2<<<dim3(CC / 64, ML / 128, 1), 256>>>(p2, p2, p2, ML, CC, HID);
    }
}